// round 13
// baseline (speedup 1.0000x reference)
#include <cuda_runtime.h>
#include <cuda_fp16.h>
#include <cstdint>

// Problem constants
#define NWIN   4096
#define NTOK   64
#define CDIM   192
#define NHEAD  6
#define HDIM   32
#define NMASK  64
#define MROWS  (NWIN * NTOK)          // 262144
#define SCALE_Q 0.17677669529663687f

#define OUT0_ELEMS  ((size_t)MROWS * CDIM)
#define ATTN_ELEMS  ((size_t)NWIN * NHEAD * NTOK * NTOK)

// ---------------- device scratch (allocation-free) ----------------
static __device__ float g_bias[NHEAD * NTOK * NTOK];

static __device__ __half g_o[MROWS * CDIM];          // attn output, single fp16
static __device__ __half g_wq[3 * CDIM * CDIM];      // weights, single fp16
static __device__ __half g_wp[CDIM * CDIM];

// ---------------- helpers ----------------
__device__ __forceinline__ uint32_t smem_u32(const void* p) {
    uint32_t a;
    asm("{ .reg .u64 t; cvta.to.shared.u64 t, %1; cvt.u32.u64 %0, t; }" : "=r"(a) : "l"(p));
    return a;
}
__device__ __forceinline__ void ldsm4(uint32_t (&r)[4], uint32_t a) {
    asm volatile("ldmatrix.sync.aligned.m8n8.x4.shared.b16 {%0,%1,%2,%3}, [%4];"
                 : "=r"(r[0]), "=r"(r[1]), "=r"(r[2]), "=r"(r[3]) : "r"(a));
}
__device__ __forceinline__ void ldsm4t(uint32_t (&r)[4], uint32_t a) {
    asm volatile("ldmatrix.sync.aligned.m8n8.x4.trans.shared.b16 {%0,%1,%2,%3}, [%4];"
                 : "=r"(r[0]), "=r"(r[1]), "=r"(r[2]), "=r"(r[3]) : "r"(a));
}
__device__ __forceinline__ void mma16816(float (&d)[4], const uint32_t (&a)[4],
                                         uint32_t b0, uint32_t b1) {
    asm volatile("mma.sync.aligned.m16n8k16.row.col.f32.f16.f16.f32 "
                 "{%0,%1,%2,%3}, {%4,%5,%6,%7}, {%8,%9}, {%0,%1,%2,%3};"
                 : "+f"(d[0]), "+f"(d[1]), "+f"(d[2]), "+f"(d[3])
                 : "r"(a[0]), "r"(a[1]), "r"(a[2]), "r"(a[3]), "r"(b0), "r"(b1));
}
__device__ __forceinline__ uint32_t packh(float a, float b) {
    __half2 t = __floats2half2_rn(a, b);
    return *reinterpret_cast<uint32_t*>(&t);
}
__device__ __forceinline__ void split2h(float a, float b, uint32_t& hi, uint32_t& lo) {
    __half ha = __float2half_rn(a), hb = __float2half_rn(b);
    float ra = a - __half2float(ha);
    float rb = b - __half2float(hb);
    __half2 th = __halves2half2(ha, hb);
    hi = *reinterpret_cast<uint32_t*>(&th);
    lo = packh(ra, rb);
}
__device__ __forceinline__ void cpasync16(uint32_t dst, const void* src) {
    asm volatile("cp.async.cg.shared.global [%0], [%1], 16;" :: "r"(dst), "l"(src));
}

// ---------------- bias gather ----------------
__global__ void bias_kernel(const float* __restrict__ table) {
    int e = blockIdx.x * 256 + threadIdx.x;
    int h  = e >> 12;
    int nm = e & 4095;
    int n = nm >> 6, m = nm & 63;
    int idx = ((n >> 3) - (m >> 3) + 7) * 15 + ((n & 7) - (m & 7) + 7);
    g_bias[e] = table[idx * NHEAD + h];
}

// ---------------- fp32 -> single fp16 (weights) ----------------
template<int DST>
__global__ void __launch_bounds__(256)
convert_kernel(const float* __restrict__ src, int n4) {
    int i = blockIdx.x * 256 + threadIdx.x;
    if (i >= n4) return;
    __half* dst = (DST == 1) ? g_wq : g_wp;
    float4 v = reinterpret_cast<const float4*>(src)[i];
    reinterpret_cast<uint2*>(dst)[i] =
        make_uint2(packh(v.x, v.y), packh(v.z, v.w));
}

// ================== FUSED QKV + ATTENTION (256 threads, 2 CTAs/SM) =========
// Smem map (bytes):
//  [0, 24576)        A single fp16 (64x192, 384B rows) -> reused for V
//  [24576, 61440)    B ring: 3 x 12288, 192x32 fp16, 64B rows
//  [61440, 86016)    Q single (per-head layout: 4096 B per head)
//  [86016, 110592)   K single (per-head layout)
#define FA    0
#define FB    24576
#define FB_ST 12288
#define FQ    61440
#define FK    86016
#define FV    0
#define FUSED_SMEM 110592

// load W chunk (s, kk32): 192 rows x 32 fp16, 64B swizzled rows
__device__ __forceinline__ void issueB32(uint32_t sb, int tid, int s, int kk, int buf) {
    uint32_t dstb = sb + FB + buf * FB_ST;
#pragma unroll
    for (int i = 0; i < 3; i++) {
        int idx = tid + i * 256;          // 0..767
        int row = idx >> 2, c = idx & 3;
        size_t src = (size_t)(s * CDIM + row) * CDIM + kk * 32 + c * 8;
        cpasync16(dstb + row * 64 + ((c ^ ((row >> 1) & 3)) << 4), g_wq + src);
    }
    asm volatile("cp.async.commit_group;" ::: "memory");
}

__global__ void __launch_bounds__(256, 2)
fused_kernel(const float* __restrict__ X, const float* __restrict__ qkv_b,
             const float* __restrict__ mask, float* __restrict__ attn_out) {
    extern __shared__ char sm[];
    const uint32_t sb = smem_u32(sm);
    const int tid = threadIdx.x;
    const int wid = tid >> 5, lane = tid & 31;
    const int b = blockIdx.x;
    const int mBase = b * 64;
    const int g = lane >> 3, rl = lane & 7;

    issueB32(sb, tid, 0, 0, 0);
    issueB32(sb, tid, 0, 1, 1);

    // load A: 64 rows x 192 fp32 -> single fp16, swizzled (3 subtiles of 64 cols)
#pragma unroll
    for (int i = 0; i < 6; i++) {
        int idx = tid + i * 256;          // 0..1535
        int row = idx / 24, cc = idx % 24;
        const float* srcp = X + (size_t)(mBase + row) * CDIM + cc * 8;
        float4 f0 = *reinterpret_cast<const float4*>(srcp);
        float4 f1 = *reinterpret_cast<const float4*>(srcp + 4);
        uint32_t h0 = packh(f0.x, f0.y);
        uint32_t h1 = packh(f0.z, f0.w);
        uint32_t h2 = packh(f1.x, f1.y);
        uint32_t h3 = packh(f1.z, f1.w);
        int sub = cc >> 3, ch = cc & 7;
        uint32_t d = row * 384 + sub * 128 + ((ch ^ (row & 7)) << 4);
        *reinterpret_cast<uint4*>(sm + FA + d) = make_uint4(h0, h1, h2, h3);
    }

    // Phase-1 warp mapping: 8 warps, warp tile 32(M) x 48(N)
    const int aRow0 = (wid >> 2) * 32 + ((g & 1) << 3) + rl;
    const int aChG  = g >> 1;
    const int bRow0 = (wid & 3) * 48 + ((g >> 1) << 3) + rl;
    const int bChG  = g & 1;

    float acc[2][6][4];

    // ---------------- Phase 1: QKV GEMM, 18 K32-chunks, single fp16 ----------
    for (int cur = 0; cur < 18; cur++) {
        const int s = cur / 6, kk = cur % 6;
        if (kk == 0) {
#pragma unroll
            for (int a = 0; a < 2; a++)
#pragma unroll
                for (int b2 = 0; b2 < 6; b2++)
#pragma unroll
                    for (int c = 0; c < 4; c++) acc[a][b2][c] = 0.0f;
        }
        if (cur < 17) { asm volatile("cp.async.wait_group 1;" ::: "memory"); }
        else          { asm volatile("cp.async.wait_group 0;" ::: "memory"); }
        __syncthreads();
        if (cur + 2 < 18) {
            int nxt = cur + 2;
            issueB32(sb, tid, nxt / 6, nxt % 6, nxt % 3);
        }
        const uint32_t bufb = sb + FB + (cur % 3) * FB_ST;
        const int sub = kk >> 1;

#pragma unroll
        for (int ks = 0; ks < 2; ks++) {
            uint32_t af[2][4], bf[3][4];
            const int chA = 2 * ((kk & 1) * 2 + ks) + aChG;
#pragma unroll
            for (int mt = 0; mt < 2; mt++) {
                int row = aRow0 + mt * 16;
                ldsm4(af[mt], sb + FA + row * 384 + sub * 128 + ((chA ^ (row & 7)) << 4));
            }
            const int chB = 2 * ks + bChG;
#pragma unroll
            for (int p = 0; p < 3; p++) {
                int row = bRow0 + p * 16;
                ldsm4(bf[p], bufb + row * 64 + ((chB ^ ((row >> 1) & 3)) << 4));
            }
#pragma unroll
            for (int p = 0; p < 3; p++)
#pragma unroll
                for (int mt = 0; mt < 2; mt++) {
                    mma16816(acc[mt][2 * p],     af[mt], bf[p][0], bf[p][1]);
                    mma16816(acc[mt][2 * p + 1], af[mt], bf[p][2], bf[p][3]);
                }
        }

        if (kk == 5) {
            // epilogue: write this s's 64x192 into smem per-head layout (single fp16)
            if (s == 2) __syncthreads();    // all warps done reading A before V overwrite
            const float sc = (s == 0) ? SCALE_Q : 1.0f;
            const uint32_t dbase = (s == 0) ? FQ : (s == 1) ? FK : FV;
#pragma unroll
            for (int mt = 0; mt < 2; mt++) {
#pragma unroll
                for (int nt = 0; nt < 6; nt++) {
                    int col = (wid & 3) * 48 + nt * 8 + (lane & 3) * 2;
                    float b0 = qkv_b[s * CDIM + col];
                    float b1 = qkv_b[s * CDIM + col + 1];
                    int hh = col >> 5, d = col & 31;
#pragma unroll
                    for (int rh = 0; rh < 2; rh++) {
                        int t = (wid >> 2) * 32 + mt * 16 + (lane >> 2) + rh * 8;
                        float v0 = (acc[mt][nt][2 * rh + 0] + b0) * sc;
                        float v1 = (acc[mt][nt][2 * rh + 1] + b1) * sc;
                        uint32_t off = hh * 4096 + t * 64 +
                                       (((d >> 3) ^ ((t >> 1) & 3)) << 4) + (d & 7) * 2;
                        *reinterpret_cast<uint32_t*>(sm + dbase + off) = packh(v0, v1);
                    }
                }
            }
        }
    }
    __syncthreads();

    // ---------------- Phase 2: attention, 2 teams x 3 iterations ----------------
    const int team = wid >> 2;
    const int wrow = wid & 3;
    const int r0 = wrow * 16 + (lane >> 2);
    const int q2 = (lane & 3) * 2;
    const float* mp = mask + ((size_t)(b & (NMASK - 1)) << 12);

#pragma unroll
    for (int it = 0; it < 3; it++) {
        const int h = 2 * it + team;
        const uint32_t qoff = h * 4096;
        const float* bp = g_bias + ((size_t)h << 12);

        // init S directly with bias + mask
        float S[8][4];
#pragma unroll
        for (int t = 0; t < 8; t++) {
            int cc = 8 * t + q2;
            float2 b0 = *reinterpret_cast<const float2*>(bp + r0 * 64 + cc);
            float2 b1 = *reinterpret_cast<const float2*>(bp + (r0 + 8) * 64 + cc);
            float2 m0 = *reinterpret_cast<const float2*>(mp + r0 * 64 + cc);
            float2 m1 = *reinterpret_cast<const float2*>(mp + (r0 + 8) * 64 + cc);
            S[t][0] = b0.x + m0.x; S[t][1] = b0.y + m0.y;
            S[t][2] = b1.x + m1.x; S[t][3] = b1.y + m1.y;
        }

        // S = Q K^T: single pass (Q single x K single)
        const uint32_t qb = sb + FQ + qoff;
        const uint32_t kb = sb + FK + qoff;
#pragma unroll
        for (int ks = 0; ks < 2; ks++) {
            uint32_t Qf[4];
            {
                int qrow = wrow * 16 + ((g & 1) << 3) + rl;
                int qc = (2 * ks + (g >> 1)) ^ ((qrow >> 1) & 3);
                ldsm4(Qf, qb + qrow * 64 + (qc << 4));
            }
#pragma unroll
            for (int nt2 = 0; nt2 < 4; nt2++) {
                uint32_t Kfr[4];
                int row = nt2 * 16 + ((g >> 1) << 3) + rl;
                int c = (2 * ks + (g & 1)) ^ ((row >> 1) & 3);
                ldsm4(Kfr, kb + row * 64 + (c << 4));
                mma16816(S[2 * nt2],     Qf, Kfr[0], Kfr[1]);
                mma16816(S[2 * nt2 + 1], Qf, Kfr[2], Kfr[3]);
            }
        }

        // softmax on fragments
        float mlo = -1e30f, mhi = -1e30f;
#pragma unroll
        for (int t = 0; t < 8; t++) {
            mlo = fmaxf(mlo, fmaxf(S[t][0], S[t][1]));
            mhi = fmaxf(mhi, fmaxf(S[t][2], S[t][3]));
        }
#pragma unroll
        for (int off = 1; off < 4; off <<= 1) {
            mlo = fmaxf(mlo, __shfl_xor_sync(0xffffffffu, mlo, off));
            mhi = fmaxf(mhi, __shfl_xor_sync(0xffffffffu, mhi, off));
        }
        float slo = 0.0f, shi = 0.0f;
#pragma unroll
        for (int t = 0; t < 8; t++) {
            S[t][0] = __expf(S[t][0] - mlo); S[t][1] = __expf(S[t][1] - mlo);
            S[t][2] = __expf(S[t][2] - mhi); S[t][3] = __expf(S[t][3] - mhi);
            slo += S[t][0] + S[t][1];
            shi += S[t][2] + S[t][3];
        }
#pragma unroll
        for (int off = 1; off < 4; off <<= 1) {
            slo += __shfl_xor_sync(0xffffffffu, slo, off);
            shi += __shfl_xor_sync(0xffffffffu, shi, off);
        }
        const float ilo = 1.0f / slo, ihi = 1.0f / shi;

        // normalize, write attn, build P fragments (fp16 hi/lo)
        const size_t ab = ((size_t)b * NHEAD + h) << 12;
        uint32_t Ph[4][4], Pl[4][4];
#pragma unroll
        for (int t = 0; t < 8; t++) {
            S[t][0] *= ilo; S[t][1] *= ilo;
            S[t][2] *= ihi; S[t][3] *= ihi;
            *reinterpret_cast<float2*>(attn_out + ab + (size_t)r0 * 64 + 8 * t + q2)
                = make_float2(S[t][0], S[t][1]);
            *reinterpret_cast<float2*>(attn_out + ab + (size_t)(r0 + 8) * 64 + 8 * t + q2)
                = make_float2(S[t][2], S[t][3]);
        }
#pragma unroll
        for (int kt = 0; kt < 4; kt++) {
            split2h(S[2 * kt][0],     S[2 * kt][1],     Ph[kt][0], Pl[kt][0]);
            split2h(S[2 * kt][2],     S[2 * kt][3],     Ph[kt][1], Pl[kt][1]);
            split2h(S[2 * kt + 1][0], S[2 * kt + 1][1], Ph[kt][2], Pl[kt][2]);
            split2h(S[2 * kt + 1][2], S[2 * kt + 1][3], Ph[kt][3], Pl[kt][3]);
        }

        // O = P V: P hi/lo x V single (V lives in old A region)
        float O[4][4];
#pragma unroll
        for (int t = 0; t < 4; t++)
#pragma unroll
            for (int j = 0; j < 4; j++) O[t][j] = 0.0f;

        const uint32_t vb = sb + FV + qoff;
#pragma unroll
        for (int kt = 0; kt < 4; kt++) {
            uint32_t bf0[4], bf1[4];
            int row = kt * 16 + ((g & 1) << 3) + rl;
            int c0 = (0 + (g >> 1)) ^ ((row >> 1) & 3);
            int c1 = (2 + (g >> 1)) ^ ((row >> 1) & 3);
            ldsm4t(bf0, vb + row * 64 + (c0 << 4));
            ldsm4t(bf1, vb + row * 64 + (c1 << 4));
            mma16816(O[0], Ph[kt], bf0[0], bf0[1]);
            mma16816(O[1], Ph[kt], bf0[2], bf0[3]);
            mma16816(O[2], Ph[kt], bf1[0], bf1[1]);
            mma16816(O[3], Ph[kt], bf1[2], bf1[3]);
            mma16816(O[0], Pl[kt], bf0[0], bf0[1]);
            mma16816(O[1], Pl[kt], bf0[2], bf0[3]);
            mma16816(O[2], Pl[kt], bf1[0], bf1[1]);
            mma16816(O[3], Pl[kt], bf1[2], bf1[3]);
        }

        // write O as single fp16, layout [b][tok][h*32+d]
        const size_t ob = (size_t)b * NTOK * CDIM + h * HDIM;
#pragma unroll
        for (int dt = 0; dt < 4; dt++) {
            int col = 8 * dt + q2;
            *reinterpret_cast<uint32_t*>(g_o + ob + (size_t)r0 * CDIM + col)
                = packh(O[dt][0], O[dt][1]);
            *reinterpret_cast<uint32_t*>(g_o + ob + (size_t)(r0 + 8) * CDIM + col)
                = packh(O[dt][2], O[dt][3]);
        }
    }
}

// ---------------- proj GEMM: O (fp16 single) x Wp (fp16 single) ----------------
#define SMA  0
#define SMB  8192
#define GEMM_SMEM 32768

__global__ void __launch_bounds__(256, 2)
proj_gemm(const float* __restrict__ bias, float* __restrict__ out) {
    extern __shared__ char sm[];
    const int tid = threadIdx.x;
    const int wid = tid >> 5, lane = tid & 31;
    const int mBase = blockIdx.y * 64;

    const uint32_t sb = smem_u32(sm);

    float acc[2][6][4];
#pragma unroll
    for (int a = 0; a < 2; a++)
#pragma unroll
        for (int b = 0; b < 6; b++)
#pragma unroll
            for (int c = 0; c < 4; c++) acc[a][b][c] = 0.0f;

    const int g  = lane >> 3, rl = lane & 7;
    const int aRow0 = (wid >> 2) * 32 + ((g & 1) << 3) + rl;
    const int aChG  = g >> 1;
    const int bRow0 = (wid & 3) * 48 + ((g >> 1) << 3) + rl;
    const int bChG  = g & 1;

    for (int kc = 0; kc < 3; kc++) {
#pragma unroll
        for (int i = 0; i < 2; i++) {
            int idx = tid + i * 256;
            int row = idx >> 3, ch = idx & 7;
            size_t src = (size_t)(mBase + row) * CDIM + kc * 64 + ch * 8;
            uint32_t dst = row * 128 + ((ch ^ (row & 7)) << 4);
            *reinterpret_cast<uint4*>(sm + SMA + dst) =
                *reinterpret_cast<const uint4*>(g_o + src);
        }
#pragma unroll
        for (int i = 0; i < 6; i++) {
            int idx = tid + i * 256;
            int row = idx >> 3, ch = idx & 7;
            size_t src = (size_t)row * CDIM + kc * 64 + ch * 8;
            uint32_t dst = row * 128 + ((ch ^ (row & 7)) << 4);
            *reinterpret_cast<uint4*>(sm + SMB + dst) =
                *reinterpret_cast<const uint4*>(g_wp + src);
        }
        __syncthreads();

#pragma unroll
        for (int ks = 0; ks < 4; ks++) {
            uint32_t af[2][4], bf[3][4];
            const int chA = 2 * ks + aChG;
#pragma unroll
            for (int mt = 0; mt < 2; mt++) {
                int row = aRow0 + mt * 16;
                ldsm4(af[mt], sb + SMA + row * 128 + ((chA ^ (row & 7)) << 4));
            }
            const int chB = 2 * ks + bChG;
#pragma unroll
            for (int p = 0; p < 3; p++) {
                int row = bRow0 + p * 16;
                ldsm4(bf[p], sb + SMB + row * 128 + ((chB ^ (row & 7)) << 4));
            }
#pragma unroll
            for (int p = 0; p < 3; p++)
#pragma unroll
                for (int mt = 0; mt < 2; mt++) {
                    mma16816(acc[mt][2 * p],     af[mt], bf[p][0], bf[p][1]);
                    mma16816(acc[mt][2 * p + 1], af[mt], bf[p][2], bf[p][3]);
                }
        }
        __syncthreads();
    }

#pragma unroll
    for (int mt = 0; mt < 2; mt++) {
#pragma unroll
        for (int nt = 0; nt < 6; nt++) {
            int col = (wid & 3) * 48 + nt * 8 + (lane & 3) * 2;
            float b0 = bias[col];
            float b1 = bias[col + 1];
#pragma unroll
            for (int rh = 0; rh < 2; rh++) {
                int t = (wid >> 2) * 32 + mt * 16 + (lane >> 2) + rh * 8;
                float v0 = acc[mt][nt][2 * rh + 0] + b0;
                float v1 = acc[mt][nt][2 * rh + 1] + b1;
                *reinterpret_cast<float2*>(out + (size_t)(mBase + t) * CDIM + col)
                    = make_float2(v0, v1);
            }
        }
    }
}

// ---------------------------------------------------------------------------
extern "C" void kernel_launch(void* const* d_in, const int* in_sizes, int n_in,
                              void* d_out, int out_size) {
    const float* x      = (const float*)d_in[0];
    const float* mask   = (const float*)d_in[1];
    const float* qkv_w  = (const float*)d_in[2];
    const float* qkv_b  = (const float*)d_in[3];
    const float* proj_w = (const float*)d_in[4];
    const float* proj_b = (const float*)d_in[5];
    const float* table  = (const float*)d_in[6];

    float* out = (float*)d_out;
    float* attn_out = out + OUT0_ELEMS;

    cudaFuncSetAttribute(fused_kernel, cudaFuncAttributeMaxDynamicSharedMemorySize, FUSED_SMEM);
    cudaFuncSetAttribute(proj_gemm, cudaFuncAttributeMaxDynamicSharedMemorySize, GEMM_SMEM);

    bias_kernel<<<96, 256>>>(table);
    {
        int w4 = (3 * CDIM * CDIM) / 4;
        convert_kernel<1><<<(w4 + 255) / 256, 256>>>(qkv_w, w4);
        int p4 = (CDIM * CDIM) / 4;
        convert_kernel<2><<<(p4 + 255) / 256, 256>>>(proj_w, p4);
    }

    fused_kernel<<<NWIN, 256, FUSED_SMEM>>>(x, qkv_b, mask, attn_out);
    proj_gemm<<<dim3(1, NWIN), 256, GEMM_SMEM>>>(proj_b, out);

    (void)in_sizes; (void)n_in; (void)out_size;
}

// round 14
// speedup vs baseline: 1.3740x; 1.3740x over previous
#include <cuda_runtime.h>
#include <cuda_fp16.h>
#include <cstdint>

// Problem constants
#define NWIN   4096
#define NTOK   64
#define CDIM   192
#define NHEAD  6
#define HDIM   32
#define NMASK  64
#define MROWS  (NWIN * NTOK)          // 262144
#define SCALE_Q 0.17677669529663687f

#define OUT0_ELEMS  ((size_t)MROWS * CDIM)
#define ATTN_ELEMS  ((size_t)NWIN * NHEAD * NTOK * NTOK)

// ---------------- device scratch (allocation-free) ----------------
static __device__ float g_bias[NHEAD * NTOK * NTOK];

static __device__ __half g_o[MROWS * CDIM];          // attn output, single fp16
static __device__ __half g_wq[3 * CDIM * CDIM];      // weights, single fp16
static __device__ __half g_wp[CDIM * CDIM];

// ---------------- helpers ----------------
__device__ __forceinline__ uint32_t smem_u32(const void* p) {
    uint32_t a;
    asm("{ .reg .u64 t; cvta.to.shared.u64 t, %1; cvt.u32.u64 %0, t; }" : "=r"(a) : "l"(p));
    return a;
}
__device__ __forceinline__ void ldsm4(uint32_t (&r)[4], uint32_t a) {
    asm volatile("ldmatrix.sync.aligned.m8n8.x4.shared.b16 {%0,%1,%2,%3}, [%4];"
                 : "=r"(r[0]), "=r"(r[1]), "=r"(r[2]), "=r"(r[3]) : "r"(a));
}
__device__ __forceinline__ void ldsm4t(uint32_t (&r)[4], uint32_t a) {
    asm volatile("ldmatrix.sync.aligned.m8n8.x4.trans.shared.b16 {%0,%1,%2,%3}, [%4];"
                 : "=r"(r[0]), "=r"(r[1]), "=r"(r[2]), "=r"(r[3]) : "r"(a));
}
__device__ __forceinline__ void mma16816(float (&d)[4], const uint32_t (&a)[4],
                                         uint32_t b0, uint32_t b1) {
    asm volatile("mma.sync.aligned.m16n8k16.row.col.f32.f16.f16.f32 "
                 "{%0,%1,%2,%3}, {%4,%5,%6,%7}, {%8,%9}, {%0,%1,%2,%3};"
                 : "+f"(d[0]), "+f"(d[1]), "+f"(d[2]), "+f"(d[3])
                 : "r"(a[0]), "r"(a[1]), "r"(a[2]), "r"(a[3]), "r"(b0), "r"(b1));
}
__device__ __forceinline__ uint32_t packh(float a, float b) {
    __half2 t = __floats2half2_rn(a, b);
    return *reinterpret_cast<uint32_t*>(&t);
}
__device__ __forceinline__ void split2h(float a, float b, uint32_t& hi, uint32_t& lo) {
    __half ha = __float2half_rn(a), hb = __float2half_rn(b);
    float ra = a - __half2float(ha);
    float rb = b - __half2float(hb);
    __half2 th = __halves2half2(ha, hb);
    hi = *reinterpret_cast<uint32_t*>(&th);
    lo = packh(ra, rb);
}
__device__ __forceinline__ void cpasync16(uint32_t dst, const void* src) {
    asm volatile("cp.async.cg.shared.global [%0], [%1], 16;" :: "r"(dst), "l"(src));
}

// ---------------- bias gather ----------------
__global__ void bias_kernel(const float* __restrict__ table) {
    int e = blockIdx.x * 256 + threadIdx.x;
    int h  = e >> 12;
    int nm = e & 4095;
    int n = nm >> 6, m = nm & 63;
    int idx = ((n >> 3) - (m >> 3) + 7) * 15 + ((n & 7) - (m & 7) + 7);
    g_bias[e] = table[idx * NHEAD + h];
}

// ---------------- fp32 -> single fp16 (weights) ----------------
template<int DST>
__global__ void __launch_bounds__(256)
convert_kernel(const float* __restrict__ src, int n4) {
    int i = blockIdx.x * 256 + threadIdx.x;
    if (i >= n4) return;
    __half* dst = (DST == 1) ? g_wq : g_wp;
    float4 v = reinterpret_cast<const float4*>(src)[i];
    reinterpret_cast<uint2*>(dst)[i] =
        make_uint2(packh(v.x, v.y), packh(v.z, v.w));
}

// ================== FUSED QKV + ATTENTION (256 threads, 1 CTA/SM) ==========
// Smem map (bytes):
//  [0, 24576)         A single fp16 (64x192, 384B rows) -> reused for V
//  [24576, 98304)     B ring: 3 x 24576, 192x64 fp16, 128B rows
//  [98304, 122880)    Q single (per-head layout, 4096 B per head)
//  [122880, 147456)   K single (per-head layout)
#define FA    0
#define FB    24576
#define FB_ST 24576
#define FQ    98304
#define FK    122880
#define FV    0
#define FUSED_SMEM 147456

// load W chunk (s, kk64): 192 rows x 64 fp16, 128B swizzled rows
__device__ __forceinline__ void issueB64(uint32_t sb, int tid, int s, int kk, int buf) {
    uint32_t dstb = sb + FB + buf * FB_ST;
#pragma unroll
    for (int i = 0; i < 6; i++) {
        int idx = tid + i * 256;          // 0..1535
        int row = idx >> 3, ch = idx & 7;
        size_t src = (size_t)(s * CDIM + row) * CDIM + kk * 64 + ch * 8;
        cpasync16(dstb + row * 128 + ((ch ^ (row & 7)) << 4), g_wq + src);
    }
    asm volatile("cp.async.commit_group;" ::: "memory");
}

__global__ void __launch_bounds__(256, 1)
fused_kernel(const float* __restrict__ X, const float* __restrict__ qkv_b,
             const float* __restrict__ mask, float* __restrict__ attn_out) {
    extern __shared__ char sm[];
    const uint32_t sb = smem_u32(sm);
    const int tid = threadIdx.x;
    const int wid = tid >> 5, lane = tid & 31;
    const int b = blockIdx.x;
    const int mBase = b * 64;
    const int g = lane >> 3, rl = lane & 7;

    issueB64(sb, tid, 0, 0, 0);
    issueB64(sb, tid, 0, 1, 1);

    // load A: 64 rows x 192 fp32 -> single fp16, swizzled (3 subtiles of 64 cols)
#pragma unroll
    for (int i = 0; i < 6; i++) {
        int idx = tid + i * 256;          // 0..1535
        int row = idx / 24, cc = idx % 24;
        const float* srcp = X + (size_t)(mBase + row) * CDIM + cc * 8;
        float4 f0 = *reinterpret_cast<const float4*>(srcp);
        float4 f1 = *reinterpret_cast<const float4*>(srcp + 4);
        uint32_t h0 = packh(f0.x, f0.y);
        uint32_t h1 = packh(f0.z, f0.w);
        uint32_t h2 = packh(f1.x, f1.y);
        uint32_t h3 = packh(f1.z, f1.w);
        int sub = cc >> 3, ch = cc & 7;
        uint32_t d = row * 384 + sub * 128 + ((ch ^ (row & 7)) << 4);
        *reinterpret_cast<uint4*>(sm + FA + d) = make_uint4(h0, h1, h2, h3);
    }

    // Phase-1 warp mapping: 8 warps, warp tile 32(M) x 48(N)
    const int aRow0 = (wid >> 2) * 32 + ((g & 1) << 3) + rl;
    const int aChG  = g >> 1;
    const int bRow0 = (wid & 3) * 48 + ((g >> 1) << 3) + rl;
    const int bChG  = g & 1;

    float acc[2][6][4];

    // ---------------- Phase 1: QKV GEMM, 9 K64-chunks, single fp16 ----------
    for (int cur = 0; cur < 9; cur++) {
        const int s = cur / 3, kk = cur % 3;
        if (kk == 0) {
#pragma unroll
            for (int a = 0; a < 2; a++)
#pragma unroll
                for (int b2 = 0; b2 < 6; b2++)
#pragma unroll
                    for (int c = 0; c < 4; c++) acc[a][b2][c] = 0.0f;
        }
        if (cur < 8) { asm volatile("cp.async.wait_group 1;" ::: "memory"); }
        else         { asm volatile("cp.async.wait_group 0;" ::: "memory"); }
        __syncthreads();
        if (cur + 2 < 9) {
            int nxt = cur + 2;
            issueB64(sb, tid, nxt / 3, nxt % 3, nxt % 3);
        }
        const uint32_t bufb = sb + FB + (cur % 3) * FB_ST;
        const uint32_t aB = sb + FA + kk * 128;

#pragma unroll
        for (int ks = 0; ks < 4; ks++) {
            uint32_t af[2][4], bf[3][4];
            const int chA = 2 * ks + aChG;
#pragma unroll
            for (int mt = 0; mt < 2; mt++) {
                int row = aRow0 + mt * 16;
                ldsm4(af[mt], aB + row * 384 + ((chA ^ (row & 7)) << 4));
            }
            const int chB = 2 * ks + bChG;
#pragma unroll
            for (int p = 0; p < 3; p++) {
                int row = bRow0 + p * 16;
                ldsm4(bf[p], bufb + row * 128 + ((chB ^ (row & 7)) << 4));
            }
#pragma unroll
            for (int p = 0; p < 3; p++)
#pragma unroll
                for (int mt = 0; mt < 2; mt++) {
                    mma16816(acc[mt][2 * p],     af[mt], bf[p][0], bf[p][1]);
                    mma16816(acc[mt][2 * p + 1], af[mt], bf[p][2], bf[p][3]);
                }
        }

        if (kk == 2) {
            // epilogue: write this s's 64x192 into smem per-head layout (single fp16)
            if (s == 2) __syncthreads();    // all warps done reading A before V overwrite
            const float sc = (s == 0) ? SCALE_Q : 1.0f;
            const uint32_t dbase = (s == 0) ? FQ : (s == 1) ? FK : FV;
#pragma unroll
            for (int mt = 0; mt < 2; mt++) {
#pragma unroll
                for (int nt = 0; nt < 6; nt++) {
                    int col = (wid & 3) * 48 + nt * 8 + (lane & 3) * 2;
                    float b0 = qkv_b[s * CDIM + col];
                    float b1 = qkv_b[s * CDIM + col + 1];
                    int hh = col >> 5, d = col & 31;
#pragma unroll
                    for (int rh = 0; rh < 2; rh++) {
                        int t = (wid >> 2) * 32 + mt * 16 + (lane >> 2) + rh * 8;
                        float v0 = (acc[mt][nt][2 * rh + 0] + b0) * sc;
                        float v1 = (acc[mt][nt][2 * rh + 1] + b1) * sc;
                        uint32_t off = hh * 4096 + t * 64 +
                                       (((d >> 3) ^ ((t >> 1) & 3)) << 4) + (d & 7) * 2;
                        *reinterpret_cast<uint32_t*>(sm + dbase + off) = packh(v0, v1);
                    }
                }
            }
        }
    }
    __syncthreads();

    // ---------------- Phase 2: attention, 2 teams x 3 iterations ----------------
    const int team = wid >> 2;
    const int wrow = wid & 3;
    const int r0 = wrow * 16 + (lane >> 2);
    const int q2 = (lane & 3) * 2;
    const float* mp = mask + ((size_t)(b & (NMASK - 1)) << 12);

#pragma unroll
    for (int it = 0; it < 3; it++) {
        const int h = 2 * it + team;
        const uint32_t qoff = h * 4096;
        const float* bp = g_bias + ((size_t)h << 12);

        // init S directly with bias + mask
        float S[8][4];
#pragma unroll
        for (int t = 0; t < 8; t++) {
            int cc = 8 * t + q2;
            float2 b0 = *reinterpret_cast<const float2*>(bp + r0 * 64 + cc);
            float2 b1 = *reinterpret_cast<const float2*>(bp + (r0 + 8) * 64 + cc);
            float2 m0 = *reinterpret_cast<const float2*>(mp + r0 * 64 + cc);
            float2 m1 = *reinterpret_cast<const float2*>(mp + (r0 + 8) * 64 + cc);
            S[t][0] = b0.x + m0.x; S[t][1] = b0.y + m0.y;
            S[t][2] = b1.x + m1.x; S[t][3] = b1.y + m1.y;
        }

        // S = Q K^T: single pass (Q single x K single)
        const uint32_t qb = sb + FQ + qoff;
        const uint32_t kb = sb + FK + qoff;
#pragma unroll
        for (int ks = 0; ks < 2; ks++) {
            uint32_t Qf[4];
            {
                int qrow = wrow * 16 + ((g & 1) << 3) + rl;
                int qc = (2 * ks + (g >> 1)) ^ ((qrow >> 1) & 3);
                ldsm4(Qf, qb + qrow * 64 + (qc << 4));
            }
#pragma unroll
            for (int nt2 = 0; nt2 < 4; nt2++) {
                uint32_t Kfr[4];
                int row = nt2 * 16 + ((g >> 1) << 3) + rl;
                int c = (2 * ks + (g & 1)) ^ ((row >> 1) & 3);
                ldsm4(Kfr, kb + row * 64 + (c << 4));
                mma16816(S[2 * nt2],     Qf, Kfr[0], Kfr[1]);
                mma16816(S[2 * nt2 + 1], Qf, Kfr[2], Kfr[3]);
            }
        }

        // softmax on fragments
        float mlo = -1e30f, mhi = -1e30f;
#pragma unroll
        for (int t = 0; t < 8; t++) {
            mlo = fmaxf(mlo, fmaxf(S[t][0], S[t][1]));
            mhi = fmaxf(mhi, fmaxf(S[t][2], S[t][3]));
        }
#pragma unroll
        for (int off = 1; off < 4; off <<= 1) {
            mlo = fmaxf(mlo, __shfl_xor_sync(0xffffffffu, mlo, off));
            mhi = fmaxf(mhi, __shfl_xor_sync(0xffffffffu, mhi, off));
        }
        float slo = 0.0f, shi = 0.0f;
#pragma unroll
        for (int t = 0; t < 8; t++) {
            S[t][0] = __expf(S[t][0] - mlo); S[t][1] = __expf(S[t][1] - mlo);
            S[t][2] = __expf(S[t][2] - mhi); S[t][3] = __expf(S[t][3] - mhi);
            slo += S[t][0] + S[t][1];
            shi += S[t][2] + S[t][3];
        }
#pragma unroll
        for (int off = 1; off < 4; off <<= 1) {
            slo += __shfl_xor_sync(0xffffffffu, slo, off);
            shi += __shfl_xor_sync(0xffffffffu, shi, off);
        }
        const float ilo = 1.0f / slo, ihi = 1.0f / shi;

        // normalize, write attn, build P fragments (fp16 hi/lo)
        const size_t ab = ((size_t)b * NHEAD + h) << 12;
        uint32_t Ph[4][4], Pl[4][4];
#pragma unroll
        for (int t = 0; t < 8; t++) {
            S[t][0] *= ilo; S[t][1] *= ilo;
            S[t][2] *= ihi; S[t][3] *= ihi;
            *reinterpret_cast<float2*>(attn_out + ab + (size_t)r0 * 64 + 8 * t + q2)
                = make_float2(S[t][0], S[t][1]);
            *reinterpret_cast<float2*>(attn_out + ab + (size_t)(r0 + 8) * 64 + 8 * t + q2)
                = make_float2(S[t][2], S[t][3]);
        }
#pragma unroll
        for (int kt = 0; kt < 4; kt++) {
            split2h(S[2 * kt][0],     S[2 * kt][1],     Ph[kt][0], Pl[kt][0]);
            split2h(S[2 * kt][2],     S[2 * kt][3],     Ph[kt][1], Pl[kt][1]);
            split2h(S[2 * kt + 1][0], S[2 * kt + 1][1], Ph[kt][2], Pl[kt][2]);
            split2h(S[2 * kt + 1][2], S[2 * kt + 1][3], Ph[kt][3], Pl[kt][3]);
        }

        // O = P V: P hi/lo x V single (V lives in old A region)
        float O[4][4];
#pragma unroll
        for (int t = 0; t < 4; t++)
#pragma unroll
            for (int j = 0; j < 4; j++) O[t][j] = 0.0f;

        const uint32_t vb = sb + FV + qoff;
#pragma unroll
        for (int kt = 0; kt < 4; kt++) {
            uint32_t bf0[4], bf1[4];
            int row = kt * 16 + ((g & 1) << 3) + rl;
            int c0 = (0 + (g >> 1)) ^ ((row >> 1) & 3);
            int c1 = (2 + (g >> 1)) ^ ((row >> 1) & 3);
            ldsm4t(bf0, vb + row * 64 + (c0 << 4));
            ldsm4t(bf1, vb + row * 64 + (c1 << 4));
            mma16816(O[0], Ph[kt], bf0[0], bf0[1]);
            mma16816(O[1], Ph[kt], bf0[2], bf0[3]);
            mma16816(O[2], Ph[kt], bf1[0], bf1[1]);
            mma16816(O[3], Ph[kt], bf1[2], bf1[3]);
            mma16816(O[0], Pl[kt], bf0[0], bf0[1]);
            mma16816(O[1], Pl[kt], bf0[2], bf0[3]);
            mma16816(O[2], Pl[kt], bf1[0], bf1[1]);
            mma16816(O[3], Pl[kt], bf1[2], bf1[3]);
        }

        // write O as single fp16, layout [b][tok][h*32+d]
        const size_t ob = (size_t)b * NTOK * CDIM + h * HDIM;
#pragma unroll
        for (int dt = 0; dt < 4; dt++) {
            int col = 8 * dt + q2;
            *reinterpret_cast<uint32_t*>(g_o + ob + (size_t)r0 * CDIM + col)
                = packh(O[dt][0], O[dt][1]);
            *reinterpret_cast<uint32_t*>(g_o + ob + (size_t)(r0 + 8) * CDIM + col)
                = packh(O[dt][2], O[dt][3]);
        }
    }
}

// ---------------- proj GEMM: O (fp16 single) x Wp (fp16 single) ----------------
#define SMA  0
#define SMB  8192
#define GEMM_SMEM 32768

__global__ void __launch_bounds__(256, 2)
proj_gemm(const float* __restrict__ bias, float* __restrict__ out) {
    extern __shared__ char sm[];
    const int tid = threadIdx.x;
    const int wid = tid >> 5, lane = tid & 31;
    const int mBase = blockIdx.y * 64;

    const uint32_t sb = smem_u32(sm);

    float acc[2][6][4];
#pragma unroll
    for (int a = 0; a < 2; a++)
#pragma unroll
        for (int b = 0; b < 6; b++)
#pragma unroll
            for (int c = 0; c < 4; c++) acc[a][b][c] = 0.0f;

    const int g  = lane >> 3, rl = lane & 7;
    const int aRow0 = (wid >> 2) * 32 + ((g & 1) << 3) + rl;
    const int aChG  = g >> 1;
    const int bRow0 = (wid & 3) * 48 + ((g >> 1) << 3) + rl;
    const int bChG  = g & 1;

    for (int kc = 0; kc < 3; kc++) {
#pragma unroll
        for (int i = 0; i < 2; i++) {
            int idx = tid + i * 256;
            int row = idx >> 3, ch = idx & 7;
            size_t src = (size_t)(mBase + row) * CDIM + kc * 64 + ch * 8;
            uint32_t dst = row * 128 + ((ch ^ (row & 7)) << 4);
            *reinterpret_cast<uint4*>(sm + SMA + dst) =
                *reinterpret_cast<const uint4*>(g_o + src);
        }
#pragma unroll
        for (int i = 0; i < 6; i++) {
            int idx = tid + i * 256;
            int row = idx >> 3, ch = idx & 7;
            size_t src = (size_t)row * CDIM + kc * 64 + ch * 8;
            uint32_t dst = row * 128 + ((ch ^ (row & 7)) << 4);
            *reinterpret_cast<uint4*>(sm + SMB + dst) =
                *reinterpret_cast<const uint4*>(g_wp + src);
        }
        __syncthreads();

#pragma unroll
        for (int ks = 0; ks < 4; ks++) {
            uint32_t af[2][4], bf[3][4];
            const int chA = 2 * ks + aChG;
#pragma unroll
            for (int mt = 0; mt < 2; mt++) {
                int row = aRow0 + mt * 16;
                ldsm4(af[mt], sb + SMA + row * 128 + ((chA ^ (row & 7)) << 4));
            }
            const int chB = 2 * ks + bChG;
#pragma unroll
            for (int p = 0; p < 3; p++) {
                int row = bRow0 + p * 16;
                ldsm4(bf[p], sb + SMB + row * 128 + ((chB ^ (row & 7)) << 4));
            }
#pragma unroll
            for (int p = 0; p < 3; p++)
#pragma unroll
                for (int mt = 0; mt < 2; mt++) {
                    mma16816(acc[mt][2 * p],     af[mt], bf[p][0], bf[p][1]);
                    mma16816(acc[mt][2 * p + 1], af[mt], bf[p][2], bf[p][3]);
                }
        }
        __syncthreads();
    }

#pragma unroll
    for (int mt = 0; mt < 2; mt++) {
#pragma unroll
        for (int nt = 0; nt < 6; nt++) {
            int col = (wid & 3) * 48 + nt * 8 + (lane & 3) * 2;
            float b0 = bias[col];
            float b1 = bias[col + 1];
#pragma unroll
            for (int rh = 0; rh < 2; rh++) {
                int t = (wid >> 2) * 32 + mt * 16 + (lane >> 2) + rh * 8;
                float v0 = acc[mt][nt][2 * rh + 0] + b0;
                float v1 = acc[mt][nt][2 * rh + 1] + b1;
                *reinterpret_cast<float2*>(out + (size_t)(mBase + t) * CDIM + col)
                    = make_float2(v0, v1);
            }
        }
    }
}

// ---------------------------------------------------------------------------
extern "C" void kernel_launch(void* const* d_in, const int* in_sizes, int n_in,
                              void* d_out, int out_size) {
    const float* x      = (const float*)d_in[0];
    const float* mask   = (const float*)d_in[1];
    const float* qkv_w  = (const float*)d_in[2];
    const float* qkv_b  = (const float*)d_in[3];
    const float* proj_w = (const float*)d_in[4];
    const float* proj_b = (const float*)d_in[5];
    const float* table  = (const float*)d_in[6];

    float* out = (float*)d_out;
    float* attn_out = out + OUT0_ELEMS;

    cudaFuncSetAttribute(fused_kernel, cudaFuncAttributeMaxDynamicSharedMemorySize, FUSED_SMEM);
    cudaFuncSetAttribute(proj_gemm, cudaFuncAttributeMaxDynamicSharedMemorySize, GEMM_SMEM);

    bias_kernel<<<96, 256>>>(table);
    {
        int w4 = (3 * CDIM * CDIM) / 4;
        convert_kernel<1><<<(w4 + 255) / 256, 256>>>(qkv_w, w4);
        int p4 = (CDIM * CDIM) / 4;
        convert_kernel<2><<<(p4 + 255) / 256, 256>>>(proj_w, p4);
    }

    fused_kernel<<<NWIN, 256, FUSED_SMEM>>>(x, qkv_b, mask, attn_out);
    proj_gemm<<<dim3(1, NWIN), 256, GEMM_SMEM>>>(proj_b, out);

    (void)in_sizes; (void)n_in; (void)out_size;
}

// round 15
// speedup vs baseline: 1.4126x; 1.0281x over previous
#include <cuda_runtime.h>
#include <cuda_fp16.h>
#include <cstdint>

// Problem constants
#define NWIN   4096
#define NTOK   64
#define CDIM   192
#define NHEAD  6
#define HDIM   32
#define NMASK  64
#define MROWS  (NWIN * NTOK)          // 262144
#define SCALE_Q 0.17677669529663687f

#define OUT0_ELEMS  ((size_t)MROWS * CDIM)
#define ATTN_ELEMS  ((size_t)NWIN * NHEAD * NTOK * NTOK)

// ---------------- device scratch (allocation-free) ----------------
static __device__ float g_bias[NHEAD * NTOK * NTOK];

static __device__ __half g_o[MROWS * CDIM];          // attn output, single fp16
static __device__ __half g_wq[3 * CDIM * CDIM];      // weights, single fp16
static __device__ __half g_wp[CDIM * CDIM];

// ---------------- helpers ----------------
__device__ __forceinline__ uint32_t smem_u32(const void* p) {
    uint32_t a;
    asm("{ .reg .u64 t; cvta.to.shared.u64 t, %1; cvt.u32.u64 %0, t; }" : "=r"(a) : "l"(p));
    return a;
}
__device__ __forceinline__ void ldsm4(uint32_t (&r)[4], uint32_t a) {
    asm volatile("ldmatrix.sync.aligned.m8n8.x4.shared.b16 {%0,%1,%2,%3}, [%4];"
                 : "=r"(r[0]), "=r"(r[1]), "=r"(r[2]), "=r"(r[3]) : "r"(a));
}
__device__ __forceinline__ void ldsm4t(uint32_t (&r)[4], uint32_t a) {
    asm volatile("ldmatrix.sync.aligned.m8n8.x4.trans.shared.b16 {%0,%1,%2,%3}, [%4];"
                 : "=r"(r[0]), "=r"(r[1]), "=r"(r[2]), "=r"(r[3]) : "r"(a));
}
__device__ __forceinline__ void mma16816(float (&d)[4], const uint32_t (&a)[4],
                                         uint32_t b0, uint32_t b1) {
    asm volatile("mma.sync.aligned.m16n8k16.row.col.f32.f16.f16.f32 "
                 "{%0,%1,%2,%3}, {%4,%5,%6,%7}, {%8,%9}, {%0,%1,%2,%3};"
                 : "+f"(d[0]), "+f"(d[1]), "+f"(d[2]), "+f"(d[3])
                 : "r"(a[0]), "r"(a[1]), "r"(a[2]), "r"(a[3]), "r"(b0), "r"(b1));
}
__device__ __forceinline__ uint32_t packh(float a, float b) {
    __half2 t = __floats2half2_rn(a, b);
    return *reinterpret_cast<uint32_t*>(&t);
}
__device__ __forceinline__ void split2h(float a, float b, uint32_t& hi, uint32_t& lo) {
    __half ha = __float2half_rn(a), hb = __float2half_rn(b);
    float ra = a - __half2float(ha);
    float rb = b - __half2float(hb);
    __half2 th = __halves2half2(ha, hb);
    hi = *reinterpret_cast<uint32_t*>(&th);
    lo = packh(ra, rb);
}
__device__ __forceinline__ void cpasync16(uint32_t dst, const void* src) {
    asm volatile("cp.async.cg.shared.global [%0], [%1], 16;" :: "r"(dst), "l"(src));
}

// ---------------- bias gather ----------------
__global__ void bias_kernel(const float* __restrict__ table) {
    int e = blockIdx.x * 256 + threadIdx.x;
    int h  = e >> 12;
    int nm = e & 4095;
    int n = nm >> 6, m = nm & 63;
    int idx = ((n >> 3) - (m >> 3) + 7) * 15 + ((n & 7) - (m & 7) + 7);
    g_bias[e] = table[idx * NHEAD + h];
}

// ---------------- fp32 -> single fp16 (weights) ----------------
template<int DST>
__global__ void __launch_bounds__(256)
convert_kernel(const float* __restrict__ src, int n4) {
    int i = blockIdx.x * 256 + threadIdx.x;
    if (i >= n4) return;
    __half* dst = (DST == 1) ? g_wq : g_wp;
    float4 v = reinterpret_cast<const float4*>(src)[i];
    reinterpret_cast<uint2*>(dst)[i] =
        make_uint2(packh(v.x, v.y), packh(v.z, v.w));
}

// ====== FUSED QKV + ATTENTION: 512 threads, ONE CTA = TWO windows ======
// 16 warps = 2 windows x 8 warps. B ring shared across both windows.
// Smem map (bytes):
//  [0, 49152)         A single fp16, 2 windows x (64x192, 384B rows) -> reused for V
//  [49152, 122880)    B ring: 3 x 24576, 192x64 fp16, 128B rows
//  [122880, 172032)   Q single, 2 windows x (per-head 4096 B x 6)
//  [172032, 221184)   K single, same layout
#define FA    0
#define FWIN  24576
#define FB    49152
#define FB_ST 24576
#define FQ    122880
#define FK    172032
#define FV    0
#define FUSED_SMEM 221184
#define FTHR  512

// load W chunk (s, kk64): 192 rows x 64 fp16, 128B swizzled rows
__device__ __forceinline__ void issueB64(uint32_t sb, int tid, int s, int kk, int buf) {
    uint32_t dstb = sb + FB + buf * FB_ST;
#pragma unroll
    for (int i = 0; i < 3; i++) {
        int idx = tid + i * FTHR;         // 0..1535
        int row = idx >> 3, ch = idx & 7;
        size_t src = (size_t)(s * CDIM + row) * CDIM + kk * 64 + ch * 8;
        cpasync16(dstb + row * 128 + ((ch ^ (row & 7)) << 4), g_wq + src);
    }
    asm volatile("cp.async.commit_group;" ::: "memory");
}

__global__ void __launch_bounds__(FTHR, 1)
fused_kernel(const float* __restrict__ X, const float* __restrict__ qkv_b,
             const float* __restrict__ mask, float* __restrict__ attn_out) {
    extern __shared__ char sm[];
    const uint32_t sb = smem_u32(sm);
    const int tid = threadIdx.x;
    const int wid = tid >> 5, lane = tid & 31;
    const int wwin = wid >> 3;            // window within CTA (0/1)
    const int wid7 = wid & 7;             // warp within window
    const int g = lane >> 3, rl = lane & 7;

    issueB64(sb, tid, 0, 0, 0);
    issueB64(sb, tid, 0, 1, 1);

    // load A: 2 windows x 64 rows x 192 fp32 -> single fp16, swizzled
#pragma unroll
    for (int i = 0; i < 6; i++) {
        int idx = tid + i * FTHR;         // 0..3071
        int w = idx / 1536, rem = idx % 1536;
        int row = rem / 24, cc = rem % 24;
        int gb = blockIdx.x * 2 + w;
        const float* srcp = X + ((size_t)gb * 64 + row) * CDIM + cc * 8;
        float4 f0 = *reinterpret_cast<const float4*>(srcp);
        float4 f1 = *reinterpret_cast<const float4*>(srcp + 4);
        uint32_t h0 = packh(f0.x, f0.y);
        uint32_t h1 = packh(f0.z, f0.w);
        uint32_t h2 = packh(f1.x, f1.y);
        uint32_t h3 = packh(f1.z, f1.w);
        int sub = cc >> 3, ch = cc & 7;
        uint32_t d = w * FWIN + row * 384 + sub * 128 + ((ch ^ (row & 7)) << 4);
        *reinterpret_cast<uint4*>(sm + FA + d) = make_uint4(h0, h1, h2, h3);
    }

    // Phase-1 warp mapping (within window): 8 warps, warp tile 32(M) x 48(N)
    const int aRow0 = (wid7 >> 2) * 32 + ((g & 1) << 3) + rl;
    const int aChG  = g >> 1;
    const int bRow0 = (wid7 & 3) * 48 + ((g >> 1) << 3) + rl;
    const int bChG  = g & 1;

    float acc[2][6][4];

    // ---------------- Phase 1: QKV GEMM, 9 K64-chunks ----------------
    for (int cur = 0; cur < 9; cur++) {
        const int s = cur / 3, kk = cur % 3;
        if (kk == 0) {
#pragma unroll
            for (int a = 0; a < 2; a++)
#pragma unroll
                for (int b2 = 0; b2 < 6; b2++)
#pragma unroll
                    for (int c = 0; c < 4; c++) acc[a][b2][c] = 0.0f;
        }
        if (cur < 8) { asm volatile("cp.async.wait_group 1;" ::: "memory"); }
        else         { asm volatile("cp.async.wait_group 0;" ::: "memory"); }
        __syncthreads();
        if (cur + 2 < 9) {
            int nxt = cur + 2;
            issueB64(sb, tid, nxt / 3, nxt % 3, nxt % 3);
        }
        const uint32_t bufb = sb + FB + (cur % 3) * FB_ST;
        const uint32_t aB = sb + FA + wwin * FWIN + kk * 128;

#pragma unroll
        for (int ks = 0; ks < 4; ks++) {
            uint32_t af[2][4], bf[3][4];
            const int chA = 2 * ks + aChG;
#pragma unroll
            for (int mt = 0; mt < 2; mt++) {
                int row = aRow0 + mt * 16;
                ldsm4(af[mt], aB + row * 384 + ((chA ^ (row & 7)) << 4));
            }
            const int chB = 2 * ks + bChG;
#pragma unroll
            for (int p = 0; p < 3; p++) {
                int row = bRow0 + p * 16;
                ldsm4(bf[p], bufb + row * 128 + ((chB ^ (row & 7)) << 4));
            }
#pragma unroll
            for (int p = 0; p < 3; p++)
#pragma unroll
                for (int mt = 0; mt < 2; mt++) {
                    mma16816(acc[mt][2 * p],     af[mt], bf[p][0], bf[p][1]);
                    mma16816(acc[mt][2 * p + 1], af[mt], bf[p][2], bf[p][3]);
                }
        }

        if (kk == 2) {
            // epilogue: write this s's 64x192 into smem per-head layout (single fp16)
            if (s == 2) __syncthreads();    // all warps done reading A before V overwrite
            const float sc = (s == 0) ? SCALE_Q : 1.0f;
            const uint32_t dbase = ((s == 0) ? FQ : (s == 1) ? FK : FV) + wwin * FWIN;
#pragma unroll
            for (int mt = 0; mt < 2; mt++) {
#pragma unroll
                for (int nt = 0; nt < 6; nt++) {
                    int col = (wid7 & 3) * 48 + nt * 8 + (lane & 3) * 2;
                    float b0 = qkv_b[s * CDIM + col];
                    float b1 = qkv_b[s * CDIM + col + 1];
                    int hh = col >> 5, d = col & 31;
#pragma unroll
                    for (int rh = 0; rh < 2; rh++) {
                        int t = (wid7 >> 2) * 32 + mt * 16 + (lane >> 2) + rh * 8;
                        float v0 = (acc[mt][nt][2 * rh + 0] + b0) * sc;
                        float v1 = (acc[mt][nt][2 * rh + 1] + b1) * sc;
                        uint32_t off = hh * 4096 + t * 64 +
                                       (((d >> 3) ^ ((t >> 1) & 3)) << 4) + (d & 7) * 2;
                        *reinterpret_cast<uint32_t*>(sm + dbase + off) = packh(v0, v1);
                    }
                }
            }
        }
    }
    __syncthreads();

    // ---------------- Phase 2: attention, per window 2 teams x 3 iters ---------
    const int b = blockIdx.x * 2 + wwin;
    const int team = wid7 >> 2;
    const int wrow = wid7 & 3;
    const int r0 = wrow * 16 + (lane >> 2);
    const int q2 = (lane & 3) * 2;
    const float* mp = mask + ((size_t)(b & (NMASK - 1)) << 12);

#pragma unroll
    for (int it = 0; it < 3; it++) {
        const int h = 2 * it + team;
        const uint32_t hoff = wwin * FWIN + h * 4096;
        const float* bp = g_bias + ((size_t)h << 12);

        // init S directly with bias + mask
        float S[8][4];
#pragma unroll
        for (int t = 0; t < 8; t++) {
            int cc = 8 * t + q2;
            float2 b0 = *reinterpret_cast<const float2*>(bp + r0 * 64 + cc);
            float2 b1 = *reinterpret_cast<const float2*>(bp + (r0 + 8) * 64 + cc);
            float2 m0 = *reinterpret_cast<const float2*>(mp + r0 * 64 + cc);
            float2 m1 = *reinterpret_cast<const float2*>(mp + (r0 + 8) * 64 + cc);
            S[t][0] = b0.x + m0.x; S[t][1] = b0.y + m0.y;
            S[t][2] = b1.x + m1.x; S[t][3] = b1.y + m1.y;
        }

        // S = Q K^T: single pass
        const uint32_t qb = sb + FQ + hoff;
        const uint32_t kb = sb + FK + hoff;
#pragma unroll
        for (int ks = 0; ks < 2; ks++) {
            uint32_t Qf[4];
            {
                int qrow = wrow * 16 + ((g & 1) << 3) + rl;
                int qc = (2 * ks + (g >> 1)) ^ ((qrow >> 1) & 3);
                ldsm4(Qf, qb + qrow * 64 + (qc << 4));
            }
#pragma unroll
            for (int nt2 = 0; nt2 < 4; nt2++) {
                uint32_t Kfr[4];
                int row = nt2 * 16 + ((g >> 1) << 3) + rl;
                int c = (2 * ks + (g & 1)) ^ ((row >> 1) & 3);
                ldsm4(Kfr, kb + row * 64 + (c << 4));
                mma16816(S[2 * nt2],     Qf, Kfr[0], Kfr[1]);
                mma16816(S[2 * nt2 + 1], Qf, Kfr[2], Kfr[3]);
            }
        }

        // softmax on fragments
        float mlo = -1e30f, mhi = -1e30f;
#pragma unroll
        for (int t = 0; t < 8; t++) {
            mlo = fmaxf(mlo, fmaxf(S[t][0], S[t][1]));
            mhi = fmaxf(mhi, fmaxf(S[t][2], S[t][3]));
        }
#pragma unroll
        for (int off = 1; off < 4; off <<= 1) {
            mlo = fmaxf(mlo, __shfl_xor_sync(0xffffffffu, mlo, off));
            mhi = fmaxf(mhi, __shfl_xor_sync(0xffffffffu, mhi, off));
        }
        float slo = 0.0f, shi = 0.0f;
#pragma unroll
        for (int t = 0; t < 8; t++) {
            S[t][0] = __expf(S[t][0] - mlo); S[t][1] = __expf(S[t][1] - mlo);
            S[t][2] = __expf(S[t][2] - mhi); S[t][3] = __expf(S[t][3] - mhi);
            slo += S[t][0] + S[t][1];
            shi += S[t][2] + S[t][3];
        }
#pragma unroll
        for (int off = 1; off < 4; off <<= 1) {
            slo += __shfl_xor_sync(0xffffffffu, slo, off);
            shi += __shfl_xor_sync(0xffffffffu, shi, off);
        }
        const float ilo = 1.0f / slo, ihi = 1.0f / shi;

        // normalize, write attn, build P fragments (fp16 hi/lo)
        const size_t ab = ((size_t)b * NHEAD + h) << 12;
        uint32_t Ph[4][4], Pl[4][4];
#pragma unroll
        for (int t = 0; t < 8; t++) {
            S[t][0] *= ilo; S[t][1] *= ilo;
            S[t][2] *= ihi; S[t][3] *= ihi;
            *reinterpret_cast<float2*>(attn_out + ab + (size_t)r0 * 64 + 8 * t + q2)
                = make_float2(S[t][0], S[t][1]);
            *reinterpret_cast<float2*>(attn_out + ab + (size_t)(r0 + 8) * 64 + 8 * t + q2)
                = make_float2(S[t][2], S[t][3]);
        }
#pragma unroll
        for (int kt = 0; kt < 4; kt++) {
            split2h(S[2 * kt][0],     S[2 * kt][1],     Ph[kt][0], Pl[kt][0]);
            split2h(S[2 * kt][2],     S[2 * kt][3],     Ph[kt][1], Pl[kt][1]);
            split2h(S[2 * kt + 1][0], S[2 * kt + 1][1], Ph[kt][2], Pl[kt][2]);
            split2h(S[2 * kt + 1][2], S[2 * kt + 1][3], Ph[kt][3], Pl[kt][3]);
        }

        // O = P V: P hi/lo x V single (V lives in old A region)
        float O[4][4];
#pragma unroll
        for (int t = 0; t < 4; t++)
#pragma unroll
            for (int j = 0; j < 4; j++) O[t][j] = 0.0f;

        const uint32_t vb = sb + FV + hoff;
#pragma unroll
        for (int kt = 0; kt < 4; kt++) {
            uint32_t bf0[4], bf1[4];
            int row = kt * 16 + ((g & 1) << 3) + rl;
            int c0 = (0 + (g >> 1)) ^ ((row >> 1) & 3);
            int c1 = (2 + (g >> 1)) ^ ((row >> 1) & 3);
            ldsm4t(bf0, vb + row * 64 + (c0 << 4));
            ldsm4t(bf1, vb + row * 64 + (c1 << 4));
            mma16816(O[0], Ph[kt], bf0[0], bf0[1]);
            mma16816(O[1], Ph[kt], bf0[2], bf0[3]);
            mma16816(O[2], Ph[kt], bf1[0], bf1[1]);
            mma16816(O[3], Ph[kt], bf1[2], bf1[3]);
            mma16816(O[0], Pl[kt], bf0[0], bf0[1]);
            mma16816(O[1], Pl[kt], bf0[2], bf0[3]);
            mma16816(O[2], Pl[kt], bf1[0], bf1[1]);
            mma16816(O[3], Pl[kt], bf1[2], bf1[3]);
        }

        // write O as single fp16, layout [b][tok][h*32+d]
        const size_t ob = (size_t)b * NTOK * CDIM + h * HDIM;
#pragma unroll
        for (int dt = 0; dt < 4; dt++) {
            int col = 8 * dt + q2;
            *reinterpret_cast<uint32_t*>(g_o + ob + (size_t)r0 * CDIM + col)
                = packh(O[dt][0], O[dt][1]);
            *reinterpret_cast<uint32_t*>(g_o + ob + (size_t)(r0 + 8) * CDIM + col)
                = packh(O[dt][2], O[dt][3]);
        }
    }
}

// ---------------- proj GEMM: O (fp16 single) x Wp (fp16 single) ----------------
#define SMA  0
#define SMB  8192
#define GEMM_SMEM 32768

__global__ void __launch_bounds__(256, 2)
proj_gemm(const float* __restrict__ bias, float* __restrict__ out) {
    extern __shared__ char sm[];
    const int tid = threadIdx.x;
    const int wid = tid >> 5, lane = tid & 31;
    const int mBase = blockIdx.y * 64;

    const uint32_t sb = smem_u32(sm);

    float acc[2][6][4];
#pragma unroll
    for (int a = 0; a < 2; a++)
#pragma unroll
        for (int b = 0; b < 6; b++)
#pragma unroll
            for (int c = 0; c < 4; c++) acc[a][b][c] = 0.0f;

    const int g  = lane >> 3, rl = lane & 7;
    const int aRow0 = (wid >> 2) * 32 + ((g & 1) << 3) + rl;
    const int aChG  = g >> 1;
    const int bRow0 = (wid & 3) * 48 + ((g >> 1) << 3) + rl;
    const int bChG  = g & 1;

    for (int kc = 0; kc < 3; kc++) {
#pragma unroll
        for (int i = 0; i < 2; i++) {
            int idx = tid + i * 256;
            int row = idx >> 3, ch = idx & 7;
            size_t src = (size_t)(mBase + row) * CDIM + kc * 64 + ch * 8;
            uint32_t dst = row * 128 + ((ch ^ (row & 7)) << 4);
            *reinterpret_cast<uint4*>(sm + SMA + dst) =
                *reinterpret_cast<const uint4*>(g_o + src);
        }
#pragma unroll
        for (int i = 0; i < 6; i++) {
            int idx = tid + i * 256;
            int row = idx >> 3, ch = idx & 7;
            size_t src = (size_t)row * CDIM + kc * 64 + ch * 8;
            uint32_t dst = row * 128 + ((ch ^ (row & 7)) << 4);
            *reinterpret_cast<uint4*>(sm + SMB + dst) =
                *reinterpret_cast<const uint4*>(g_wp + src);
        }
        __syncthreads();

#pragma unroll
        for (int ks = 0; ks < 4; ks++) {
            uint32_t af[2][4], bf[3][4];
            const int chA = 2 * ks + aChG;
#pragma unroll
            for (int mt = 0; mt < 2; mt++) {
                int row = aRow0 + mt * 16;
                ldsm4(af[mt], sb + SMA + row * 128 + ((chA ^ (row & 7)) << 4));
            }
            const int chB = 2 * ks + bChG;
#pragma unroll
            for (int p = 0; p < 3; p++) {
                int row = bRow0 + p * 16;
                ldsm4(bf[p], sb + SMB + row * 128 + ((chB ^ (row & 7)) << 4));
            }
#pragma unroll
            for (int p = 0; p < 3; p++)
#pragma unroll
                for (int mt = 0; mt < 2; mt++) {
                    mma16816(acc[mt][2 * p],     af[mt], bf[p][0], bf[p][1]);
                    mma16816(acc[mt][2 * p + 1], af[mt], bf[p][2], bf[p][3]);
                }
        }
        __syncthreads();
    }

#pragma unroll
    for (int mt = 0; mt < 2; mt++) {
#pragma unroll
        for (int nt = 0; nt < 6; nt++) {
            int col = (wid & 3) * 48 + nt * 8 + (lane & 3) * 2;
            float b0 = bias[col];
            float b1 = bias[col + 1];
#pragma unroll
            for (int rh = 0; rh < 2; rh++) {
                int t = (wid >> 2) * 32 + mt * 16 + (lane >> 2) + rh * 8;
                float v0 = acc[mt][nt][2 * rh + 0] + b0;
                float v1 = acc[mt][nt][2 * rh + 1] + b1;
                *reinterpret_cast<float2*>(out + (size_t)(mBase + t) * CDIM + col)
                    = make_float2(v0, v1);
            }
        }
    }
}

// ---------------------------------------------------------------------------
extern "C" void kernel_launch(void* const* d_in, const int* in_sizes, int n_in,
                              void* d_out, int out_size) {
    const float* x      = (const float*)d_in[0];
    const float* mask   = (const float*)d_in[1];
    const float* qkv_w  = (const float*)d_in[2];
    const float* qkv_b  = (const float*)d_in[3];
    const float* proj_w = (const float*)d_in[4];
    const float* proj_b = (const float*)d_in[5];
    const float* table  = (const float*)d_in[6];

    float* out = (float*)d_out;
    float* attn_out = out + OUT0_ELEMS;

    cudaFuncSetAttribute(fused_kernel, cudaFuncAttributeMaxDynamicSharedMemorySize, FUSED_SMEM);
    cudaFuncSetAttribute(proj_gemm, cudaFuncAttributeMaxDynamicSharedMemorySize, GEMM_SMEM);

    bias_kernel<<<96, 256>>>(table);
    {
        int w4 = (3 * CDIM * CDIM) / 4;
        convert_kernel<1><<<(w4 + 255) / 256, 256>>>(qkv_w, w4);
        int p4 = (CDIM * CDIM) / 4;
        convert_kernel<2><<<(p4 + 255) / 256, 256>>>(proj_w, p4);
    }

    // fused: one CTA handles two windows
    fused_kernel<<<NWIN / 2, FTHR, FUSED_SMEM>>>(x, qkv_b, mask, attn_out);
    proj_gemm<<<dim3(1, NWIN), 256, GEMM_SMEM>>>(proj_b, out);

    (void)in_sizes; (void)n_in; (void)out_size;
}

// round 17
// speedup vs baseline: 1.4268x; 1.0101x over previous
#include <cuda_runtime.h>
#include <cuda_fp16.h>
#include <cstdint>

// Problem constants
#define NWIN   4096
#define NTOK   64
#define CDIM   192
#define NHEAD  6
#define HDIM   32
#define NMASK  64
#define MROWS  (NWIN * NTOK)          // 262144
#define SCALE_Q 0.17677669529663687f

#define OUT0_ELEMS  ((size_t)MROWS * CDIM)
#define ATTN_ELEMS  ((size_t)NWIN * NHEAD * NTOK * NTOK)

// ---------------- device scratch (allocation-free) ----------------
static __device__ float g_bias[NHEAD * NTOK * NTOK];

static __device__ __half g_o[MROWS * CDIM];          // attn output, single fp16
static __device__ __half g_wq[3 * CDIM * CDIM];      // weights, single fp16
static __device__ __half g_wp[CDIM * CDIM];

// ---------------- helpers ----------------
__device__ __forceinline__ uint32_t smem_u32(const void* p) {
    uint32_t a;
    asm("{ .reg .u64 t; cvta.to.shared.u64 t, %1; cvt.u32.u64 %0, t; }" : "=r"(a) : "l"(p));
    return a;
}
__device__ __forceinline__ void ldsm4(uint32_t (&r)[4], uint32_t a) {
    asm volatile("ldmatrix.sync.aligned.m8n8.x4.shared.b16 {%0,%1,%2,%3}, [%4];"
                 : "=r"(r[0]), "=r"(r[1]), "=r"(r[2]), "=r"(r[3]) : "r"(a));
}
__device__ __forceinline__ void ldsm4t(uint32_t (&r)[4], uint32_t a) {
    asm volatile("ldmatrix.sync.aligned.m8n8.x4.trans.shared.b16 {%0,%1,%2,%3}, [%4];"
                 : "=r"(r[0]), "=r"(r[1]), "=r"(r[2]), "=r"(r[3]) : "r"(a));
}
__device__ __forceinline__ void mma16816(float (&d)[4], const uint32_t (&a)[4],
                                         uint32_t b0, uint32_t b1) {
    asm volatile("mma.sync.aligned.m16n8k16.row.col.f32.f16.f16.f32 "
                 "{%0,%1,%2,%3}, {%4,%5,%6,%7}, {%8,%9}, {%0,%1,%2,%3};"
                 : "+f"(d[0]), "+f"(d[1]), "+f"(d[2]), "+f"(d[3])
                 : "r"(a[0]), "r"(a[1]), "r"(a[2]), "r"(a[3]), "r"(b0), "r"(b1));
}
__device__ __forceinline__ uint32_t packh(float a, float b) {
    __half2 t = __floats2half2_rn(a, b);
    return *reinterpret_cast<uint32_t*>(&t);
}
__device__ __forceinline__ void cpasync16(uint32_t dst, const void* src) {
    asm volatile("cp.async.cg.shared.global [%0], [%1], 16;" :: "r"(dst), "l"(src));
}

// ---------------- bias gather ----------------
__global__ void bias_kernel(const float* __restrict__ table) {
    int e = blockIdx.x * 256 + threadIdx.x;
    int h  = e >> 12;
    int nm = e & 4095;
    int n = nm >> 6, m = nm & 63;
    int idx = ((n >> 3) - (m >> 3) + 7) * 15 + ((n & 7) - (m & 7) + 7);
    g_bias[e] = table[idx * NHEAD + h];
}

// ---------------- fp32 -> single fp16 (weights) ----------------
template<int DST>
__global__ void __launch_bounds__(256)
convert_kernel(const float* __restrict__ src, int n4) {
    int i = blockIdx.x * 256 + threadIdx.x;
    if (i >= n4) return;
    __half* dst = (DST == 1) ? g_wq : g_wp;
    float4 v = reinterpret_cast<const float4*>(src)[i];
    reinterpret_cast<uint2*>(dst)[i] =
        make_uint2(packh(v.x, v.y), packh(v.z, v.w));
}

// ====== FUSED QKV + ATTENTION: 512 threads, ONE CTA = TWO windows ======
#define FA    0
#define FWIN  24576
#define FB    49152
#define FB_ST 24576
#define FQ    122880
#define FK    172032
#define FV    0
#define FUSED_SMEM 221184
#define FTHR  512

__device__ __forceinline__ void issueB64(uint32_t sb, int tid, int s, int kk, int buf) {
    uint32_t dstb = sb + FB + buf * FB_ST;
#pragma unroll
    for (int i = 0; i < 3; i++) {
        int idx = tid + i * FTHR;         // 0..1535
        int row = idx >> 3, ch = idx & 7;
        size_t src = (size_t)(s * CDIM + row) * CDIM + kk * 64 + ch * 8;
        cpasync16(dstb + row * 128 + ((ch ^ (row & 7)) << 4), g_wq + src);
    }
    asm volatile("cp.async.commit_group;" ::: "memory");
}

__global__ void __launch_bounds__(FTHR, 1)
fused_kernel(const float* __restrict__ X, const float* __restrict__ qkv_b,
             const float* __restrict__ mask, float* __restrict__ attn_out) {
    extern __shared__ char sm[];
    const uint32_t sb = smem_u32(sm);
    const int tid = threadIdx.x;
    const int wid = tid >> 5, lane = tid & 31;
    const int wwin = wid >> 3;            // window within CTA (0/1)
    const int wid7 = wid & 7;             // warp within window
    const int g = lane >> 3, rl = lane & 7;

    issueB64(sb, tid, 0, 0, 0);
    issueB64(sb, tid, 0, 1, 1);

    // load A: 2 windows x 64 rows x 192 fp32 -> single fp16, swizzled
#pragma unroll
    for (int i = 0; i < 6; i++) {
        int idx = tid + i * FTHR;         // 0..3071
        int w = idx / 1536, rem = idx % 1536;
        int row = rem / 24, cc = rem % 24;
        int gb = blockIdx.x * 2 + w;
        const float* srcp = X + ((size_t)gb * 64 + row) * CDIM + cc * 8;
        float4 f0 = *reinterpret_cast<const float4*>(srcp);
        float4 f1 = *reinterpret_cast<const float4*>(srcp + 4);
        uint32_t h0 = packh(f0.x, f0.y);
        uint32_t h1 = packh(f0.z, f0.w);
        uint32_t h2 = packh(f1.x, f1.y);
        uint32_t h3 = packh(f1.z, f1.w);
        int sub = cc >> 3, ch = cc & 7;
        uint32_t d = w * FWIN + row * 384 + sub * 128 + ((ch ^ (row & 7)) << 4);
        *reinterpret_cast<uint4*>(sm + FA + d) = make_uint4(h0, h1, h2, h3);
    }

    // Phase-1 warp mapping (within window): 8 warps, warp tile 32(M) x 48(N)
    const int aRow0 = (wid7 >> 2) * 32 + ((g & 1) << 3) + rl;
    const int aChG  = g >> 1;
    const int bRow0 = (wid7 & 3) * 48 + ((g >> 1) << 3) + rl;
    const int bChG  = g & 1;

    float acc[2][6][4];

    // ---------------- Phase 1: QKV GEMM, 9 K64-chunks ----------------
    for (int cur = 0; cur < 9; cur++) {
        const int s = cur / 3, kk = cur % 3;
        if (kk == 0) {
#pragma unroll
            for (int a = 0; a < 2; a++)
#pragma unroll
                for (int b2 = 0; b2 < 6; b2++)
#pragma unroll
                    for (int c = 0; c < 4; c++) acc[a][b2][c] = 0.0f;
        }
        if (cur < 8) { asm volatile("cp.async.wait_group 1;" ::: "memory"); }
        else         { asm volatile("cp.async.wait_group 0;" ::: "memory"); }
        __syncthreads();
        if (cur + 2 < 9) {
            int nxt = cur + 2;
            issueB64(sb, tid, nxt / 3, nxt % 3, nxt % 3);
        }
        const uint32_t bufb = sb + FB + (cur % 3) * FB_ST;
        const uint32_t aB = sb + FA + wwin * FWIN + kk * 128;

#pragma unroll
        for (int ks = 0; ks < 4; ks++) {
            uint32_t af[2][4], bf[3][4];
            const int chA = 2 * ks + aChG;
#pragma unroll
            for (int mt = 0; mt < 2; mt++) {
                int row = aRow0 + mt * 16;
                ldsm4(af[mt], aB + row * 384 + ((chA ^ (row & 7)) << 4));
            }
            const int chB = 2 * ks + bChG;
#pragma unroll
            for (int p = 0; p < 3; p++) {
                int row = bRow0 + p * 16;
                ldsm4(bf[p], bufb + row * 128 + ((chB ^ (row & 7)) << 4));
            }
#pragma unroll
            for (int p = 0; p < 3; p++)
#pragma unroll
                for (int mt = 0; mt < 2; mt++) {
                    mma16816(acc[mt][2 * p],     af[mt], bf[p][0], bf[p][1]);
                    mma16816(acc[mt][2 * p + 1], af[mt], bf[p][2], bf[p][3]);
                }
        }

        if (kk == 2) {
            if (s == 2) __syncthreads();    // all warps done reading A before V overwrite
            const float sc = (s == 0) ? SCALE_Q : 1.0f;
            const uint32_t dbase = ((s == 0) ? FQ : (s == 1) ? FK : FV) + wwin * FWIN;
#pragma unroll
            for (int mt = 0; mt < 2; mt++) {
#pragma unroll
                for (int nt = 0; nt < 6; nt++) {
                    int col = (wid7 & 3) * 48 + nt * 8 + (lane & 3) * 2;
                    float b0 = qkv_b[s * CDIM + col];
                    float b1 = qkv_b[s * CDIM + col + 1];
                    int hh = col >> 5, d = col & 31;
#pragma unroll
                    for (int rh = 0; rh < 2; rh++) {
                        int t = (wid7 >> 2) * 32 + mt * 16 + (lane >> 2) + rh * 8;
                        float v0 = (acc[mt][nt][2 * rh + 0] + b0) * sc;
                        float v1 = (acc[mt][nt][2 * rh + 1] + b1) * sc;
                        uint32_t off = hh * 4096 + t * 64 +
                                       (((d >> 3) ^ ((t >> 1) & 3)) << 4) + (d & 7) * 2;
                        *reinterpret_cast<uint32_t*>(sm + dbase + off) = packh(v0, v1);
                    }
                }
            }
        }
    }
    __syncthreads();

    // ---------------- Phase 2: attention, per window 2 teams x 3 iters ---------
    const int b = blockIdx.x * 2 + wwin;
    const int team = wid7 >> 2;
    const int wrow = wid7 & 3;
    const int r0 = wrow * 16 + (lane >> 2);
    const int q2 = (lane & 3) * 2;
    const float* mp = mask + ((size_t)(b & (NMASK - 1)) << 12);

#pragma unroll
    for (int it = 0; it < 3; it++) {
        const int h = 2 * it + team;
        const uint32_t hoff = wwin * FWIN + h * 4096;
        const float* bp = g_bias + ((size_t)h << 12);

        // init S directly with bias + mask
        float S[8][4];
#pragma unroll
        for (int t = 0; t < 8; t++) {
            int cc = 8 * t + q2;
            float2 b0 = *reinterpret_cast<const float2*>(bp + r0 * 64 + cc);
            float2 b1 = *reinterpret_cast<const float2*>(bp + (r0 + 8) * 64 + cc);
            float2 m0 = *reinterpret_cast<const float2*>(mp + r0 * 64 + cc);
            float2 m1 = *reinterpret_cast<const float2*>(mp + (r0 + 8) * 64 + cc);
            S[t][0] = b0.x + m0.x; S[t][1] = b0.y + m0.y;
            S[t][2] = b1.x + m1.x; S[t][3] = b1.y + m1.y;
        }

        // S = Q K^T: single pass
        const uint32_t qb = sb + FQ + hoff;
        const uint32_t kb = sb + FK + hoff;
#pragma unroll
        for (int ks = 0; ks < 2; ks++) {
            uint32_t Qf[4];
            {
                int qrow = wrow * 16 + ((g & 1) << 3) + rl;
                int qc = (2 * ks + (g >> 1)) ^ ((qrow >> 1) & 3);
                ldsm4(Qf, qb + qrow * 64 + (qc << 4));
            }
#pragma unroll
            for (int nt2 = 0; nt2 < 4; nt2++) {
                uint32_t Kfr[4];
                int row = nt2 * 16 + ((g >> 1) << 3) + rl;
                int c = (2 * ks + (g & 1)) ^ ((row >> 1) & 3);
                ldsm4(Kfr, kb + row * 64 + (c << 4));
                mma16816(S[2 * nt2],     Qf, Kfr[0], Kfr[1]);
                mma16816(S[2 * nt2 + 1], Qf, Kfr[2], Kfr[3]);
            }
        }

        // softmax on fragments
        float mlo = -1e30f, mhi = -1e30f;
#pragma unroll
        for (int t = 0; t < 8; t++) {
            mlo = fmaxf(mlo, fmaxf(S[t][0], S[t][1]));
            mhi = fmaxf(mhi, fmaxf(S[t][2], S[t][3]));
        }
#pragma unroll
        for (int off = 1; off < 4; off <<= 1) {
            mlo = fmaxf(mlo, __shfl_xor_sync(0xffffffffu, mlo, off));
            mhi = fmaxf(mhi, __shfl_xor_sync(0xffffffffu, mhi, off));
        }
        float slo = 0.0f, shi = 0.0f;
#pragma unroll
        for (int t = 0; t < 8; t++) {
            S[t][0] = __expf(S[t][0] - mlo); S[t][1] = __expf(S[t][1] - mlo);
            S[t][2] = __expf(S[t][2] - mhi); S[t][3] = __expf(S[t][3] - mhi);
            slo += S[t][0] + S[t][1];
            shi += S[t][2] + S[t][3];
        }
#pragma unroll
        for (int off = 1; off < 4; off <<= 1) {
            slo += __shfl_xor_sync(0xffffffffu, slo, off);
            shi += __shfl_xor_sync(0xffffffffu, shi, off);
        }
        const float ilo = 1.0f / slo, ihi = 1.0f / shi;

        // normalize, write attn, build P fragments (single fp16)
        const size_t ab = ((size_t)b * NHEAD + h) << 12;
        uint32_t Ph[4][4];
#pragma unroll
        for (int t = 0; t < 8; t++) {
            S[t][0] *= ilo; S[t][1] *= ilo;
            S[t][2] *= ihi; S[t][3] *= ihi;
            *reinterpret_cast<float2*>(attn_out + ab + (size_t)r0 * 64 + 8 * t + q2)
                = make_float2(S[t][0], S[t][1]);
            *reinterpret_cast<float2*>(attn_out + ab + (size_t)(r0 + 8) * 64 + 8 * t + q2)
                = make_float2(S[t][2], S[t][3]);
        }
#pragma unroll
        for (int kt = 0; kt < 4; kt++) {
            Ph[kt][0] = packh(S[2 * kt][0],     S[2 * kt][1]);
            Ph[kt][1] = packh(S[2 * kt][2],     S[2 * kt][3]);
            Ph[kt][2] = packh(S[2 * kt + 1][0], S[2 * kt + 1][1]);
            Ph[kt][3] = packh(S[2 * kt + 1][2], S[2 * kt + 1][3]);
        }

        // O = P V: single pass (P fp16 x V fp16)
        float O[4][4];
#pragma unroll
        for (int t = 0; t < 4; t++)
#pragma unroll
            for (int j = 0; j < 4; j++) O[t][j] = 0.0f;

        const uint32_t vb = sb + FV + hoff;
#pragma unroll
        for (int kt = 0; kt < 4; kt++) {
            uint32_t bf0[4], bf1[4];
            int row = kt * 16 + ((g & 1) << 3) + rl;
            int c0 = (0 + (g >> 1)) ^ ((row >> 1) & 3);
            int c1 = (2 + (g >> 1)) ^ ((row >> 1) & 3);
            ldsm4t(bf0, vb + row * 64 + (c0 << 4));
            ldsm4t(bf1, vb + row * 64 + (c1 << 4));
            mma16816(O[0], Ph[kt], bf0[0], bf0[1]);
            mma16816(O[1], Ph[kt], bf0[2], bf0[3]);
            mma16816(O[2], Ph[kt], bf1[0], bf1[1]);
            mma16816(O[3], Ph[kt], bf1[2], bf1[3]);
        }

        // write O as single fp16, layout [b][tok][h*32+d]
        const size_t ob = (size_t)b * NTOK * CDIM + h * HDIM;
#pragma unroll
        for (int dt = 0; dt < 4; dt++) {
            int col = 8 * dt + q2;
            *reinterpret_cast<uint32_t*>(g_o + ob + (size_t)r0 * CDIM + col)
                = packh(O[dt][0], O[dt][1]);
            *reinterpret_cast<uint32_t*>(g_o + ob + (size_t)(r0 + 8) * CDIM + col)
                = packh(O[dt][2], O[dt][3]);
        }
    }
}

// ---------------- proj GEMM: O (fp16 single) x Wp (fp16 single) ----------------
#define SMA  0
#define SMB  8192
#define GEMM_SMEM 32768

__global__ void __launch_bounds__(256, 2)
proj_gemm(const float* __restrict__ bias, float* __restrict__ out) {
    extern __shared__ char sm[];
    const int tid = threadIdx.x;
    const int wid = tid >> 5, lane = tid & 31;
    const int mBase = blockIdx.y * 64;

    const uint32_t sb = smem_u32(sm);

    float acc[2][6][4];
#pragma unroll
    for (int a = 0; a < 2; a++)
#pragma unroll
        for (int b = 0; b < 6; b++)
#pragma unroll
            for (int c = 0; c < 4; c++) acc[a][b][c] = 0.0f;

    const int g  = lane >> 3, rl = lane & 7;
    const int aRow0 = (wid >> 2) * 32 + ((g & 1) << 3) + rl;
    const int aChG  = g >> 1;
    const int bRow0 = (wid & 3) * 48 + ((g >> 1) << 3) + rl;
    const int bChG  = g & 1;

    for (int kc = 0; kc < 3; kc++) {
#pragma unroll
        for (int i = 0; i < 2; i++) {
            int idx = tid + i * 256;
            int row = idx >> 3, ch = idx & 7;
            size_t src = (size_t)(mBase + row) * CDIM + kc * 64 + ch * 8;
            uint32_t dst = row * 128 + ((ch ^ (row & 7)) << 4);
            *reinterpret_cast<uint4*>(sm + SMA + dst) =
                *reinterpret_cast<const uint4*>(g_o + src);
        }
#pragma unroll
        for (int i = 0; i < 6; i++) {
            int idx = tid + i * 256;
            int row = idx >> 3, ch = idx & 7;
            size_t src = (size_t)row * CDIM + kc * 64 + ch * 8;
            uint32_t dst = row * 128 + ((ch ^ (row & 7)) << 4);
            *reinterpret_cast<uint4*>(sm + SMB + dst) =
                *reinterpret_cast<const uint4*>(g_wp + src);
        }
        __syncthreads();

#pragma unroll
        for (int ks = 0; ks < 4; ks++) {
            uint32_t af[2][4], bf[3][4];
            const int chA = 2 * ks + aChG;
#pragma unroll
            for (int mt = 0; mt < 2; mt++) {
                int row = aRow0 + mt * 16;
                ldsm4(af[mt], sb + SMA + row * 128 + ((chA ^ (row & 7)) << 4));
            }
            const int chB = 2 * ks + bChG;
#pragma unroll
            for (int p = 0; p < 3; p++) {
                int row = bRow0 + p * 16;
                ldsm4(bf[p], sb + SMB + row * 128 + ((chB ^ (row & 7)) << 4));
            }
#pragma unroll
            for (int p = 0; p < 3; p++)
#pragma unroll
                for (int mt = 0; mt < 2; mt++) {
                    mma16816(acc[mt][2 * p],     af[mt], bf[p][0], bf[p][1]);
                    mma16816(acc[mt][2 * p + 1], af[mt], bf[p][2], bf[p][3]);
                }
        }
        __syncthreads();
    }

#pragma unroll
    for (int mt = 0; mt < 2; mt++) {
#pragma unroll
        for (int nt = 0; nt < 6; nt++) {
            int col = (wid & 3) * 48 + nt * 8 + (lane & 3) * 2;
            float b0 = bias[col];
            float b1 = bias[col + 1];
#pragma unroll
            for (int rh = 0; rh < 2; rh++) {
                int t = (wid >> 2) * 32 + mt * 16 + (lane >> 2) + rh * 8;
                float v0 = acc[mt][nt][2 * rh + 0] + b0;
                float v1 = acc[mt][nt][2 * rh + 1] + b1;
                *reinterpret_cast<float2*>(out + (size_t)(mBase + t) * CDIM + col)
                    = make_float2(v0, v1);
            }
        }
    }
}

// ---------------------------------------------------------------------------
extern "C" void kernel_launch(void* const* d_in, const int* in_sizes, int n_in,
                              void* d_out, int out_size) {
    const float* x      = (const float*)d_in[0];
    const float* mask   = (const float*)d_in[1];
    const float* qkv_w  = (const float*)d_in[2];
    const float* qkv_b  = (const float*)d_in[3];
    const float* proj_w = (const float*)d_in[4];
    const float* proj_b = (const float*)d_in[5];
    const float* table  = (const float*)d_in[6];

    float* out = (float*)d_out;
    float* attn_out = out + OUT0_ELEMS;

    cudaFuncSetAttribute(fused_kernel, cudaFuncAttributeMaxDynamicSharedMemorySize, FUSED_SMEM);
    cudaFuncSetAttribute(proj_gemm, cudaFuncAttributeMaxDynamicSharedMemorySize, GEMM_SMEM);

    bias_kernel<<<96, 256>>>(table);
    {
        int w4 = (3 * CDIM * CDIM) / 4;
        convert_kernel<1><<<(w4 + 255) / 256, 256>>>(qkv_w, w4);
        int p4 = (CDIM * CDIM) / 4;
        convert_kernel<2><<<(p4 + 255) / 256, 256>>>(proj_w, p4);
    }

    // fused: one CTA handles two windows
    fused_kernel<<<NWIN / 2, FTHR, FUSED_SMEM>>>(x, qkv_b, mask, attn_out);
    proj_gemm<<<dim3(1, NWIN), 256, GEMM_SMEM>>>(proj_b, out);

    (void)in_sizes; (void)n_in; (void)out_size;
}